// round 12
// baseline (speedup 1.0000x reference)
#include <cuda_runtime.h>
#include <cstdint>

// Problem constants (shapes fixed by the dataset)
#define BB   64
#define KK   8
#define VV   128000
#define NS   10              // chunks per batch row (51.2 KB per row-chunk)
#define TPB  256
#define NW   (TPB / 32)      // 8 warps per block
#define LCH  (VV / NS)       // 12800 floats per chunk
#define SEG  128             // floats per segment (one warp-wide float4 iter)
#define SEGC (LCH / SEG)     // 100 segments per chunk
#define FULL 0xFFFFFFFFu

// Scratch (device globals — zero-initialized; g_done self-resets every call)
__device__ float g_ssum[BB * NS * SEGC];     // per-segment sums
__device__ float g_chunksum[BB * NS];
__device__ int   g_done[BB];

// ---------------------------------------------------------------------------
// Hierarchical CDF search for one batch (executed by warp 0 of last block).
// level 1: 10 chunk sums -> level 2: 100 segment sums -> level 3: 128 floats.
// Level-2 group-scan-with-carry order is EXACTLY the order used to build the
// chunk sums in the main kernel, so crossings are located consistently.
// ---------------------------------------------------------------------------
__device__ __forceinline__ void cdf_search(int b, int na, int allacc, int r,
                                           const float* __restrict__ dp,
                                           const float* __restrict__ op,
                                           const float* __restrict__ su,
                                           float* __restrict__ out, int lane)
{
    float cs = (lane < NS) ? __ldcg(&g_chunksum[b * NS + lane]) : 0.0f;
    float x = cs;
#pragma unroll
    for (int o = 1; o < 32; o <<= 1) {
        float y = __shfl_up_sync(FULL, x, o);
        if (lane >= o) x += y;
    }
    float tot = __shfl_sync(FULL, x, NS - 1);
    float T = allacc ? su[b] : su[b] * tot;

    unsigned bal = __ballot_sync(FULL, (lane < NS) && (x >= T));
    int token;
    if (bal == 0) {
        token = VV - 1;
    } else {
        int sc = __ffs(bal) - 1;
        float base = __shfl_sync(FULL, x, sc) - __shfl_sync(FULL, cs, sc);

        // level 2: 100 segment sums, scanned 32 at a time with carry
        const float* ss = &g_ssum[(b * NS + sc) * SEGC];
        int   j_found = -1;
        float base_t  = 0.0f;
        float running = base;
#pragma unroll
        for (int g = 0; g < 4; ++g) {
            int j = g * 32 + lane;
            float v = (j < SEGC) ? __ldcg(&ss[j]) : 0.0f;
            float xx = v;
#pragma unroll
            for (int o = 1; o < 32; o <<= 1) {
                float y = __shfl_up_sync(FULL, xx, o);
                if (lane >= o) xx += y;
            }
            unsigned bb2 = __ballot_sync(FULL, (j < SEGC) && (running + xx >= T));
            if (bb2) {
                int l = __ffs(bb2) - 1;
                j_found = g * 32 + l;
                base_t  = running + __shfl_sync(FULL, xx, l)
                                  - __shfl_sync(FULL, v, l);
                break;
            }
            running += __shfl_sync(FULL, xx, 31);
        }

        if (j_found < 0) {
            token = min(sc * LCH + LCH, VV - 1);         // ulp-tie fallback
        } else {
            // level 3: one 128-float segment, coalesced re-read
            int off0 = sc * LCH + j_found * SEG;
            int ob2  = (b * (KK + 1) + (allacc ? KK : r)) * VV + off0;
            int db2  = (b * KK + r) * VV + off0;
            float4 ov = ((const float4*)(op + ob2))[lane];
            float v0, v1, v2, v3;
            if (allacc) {
                v0 = ov.x; v1 = ov.y; v2 = ov.z; v3 = ov.w;
            } else {
                float4 dv = ((const float4*)(dp + db2))[lane];
                v0 = fmaxf(ov.x - dv.x, 0.f); v1 = fmaxf(ov.y - dv.y, 0.f);
                v2 = fmaxf(ov.z - dv.z, 0.f); v3 = fmaxf(ov.w - dv.w, 0.f);
            }
            float local = v0 + v1 + v2 + v3;
            float xs = local;
#pragma unroll
            for (int o = 1; o < 32; o <<= 1) {
                float y = __shfl_up_sync(FULL, xs, o);
                if (lane >= o) xs += y;
            }
            unsigned bb3 = __ballot_sync(FULL, base_t + xs >= T);
            if (!bb3) {
                token = min(off0 + SEG, VV - 1);          // ulp-tie fallback
            } else {
                int l = __ffs(bb3) - 1;
                float excl = base_t + __shfl_sync(FULL, xs, l)
                                    - __shfl_sync(FULL, local, l);
                float a0 = __shfl_sync(FULL, v0, l);
                float a1 = __shfl_sync(FULL, v1, l);
                float a2 = __shfl_sync(FULL, v2, l);
                float run = excl;
                int idx = 3;
                run += a0;
                if (run >= T) idx = 0;
                else { run += a1;
                    if (run >= T) idx = 1;
                    else { run += a2; if (run >= T) idx = 2; }
                }
                token = min(off0 + l * 4 + idx, VV - 1);
            }
        }
    }

    if (lane == 0)
        out[b * (KK + 1) + na] = (float)token;
}

// ---------------------------------------------------------------------------
// Fused kernel: 640 blocks x 256 threads, one 51.2KB-per-row chunk per block.
// 2.5x more streaming per block amortizes the acceptance prologue and the
// reduce/fence/atomic epilogue; grid-limited ~4.3 blocks/SM = single wave.
// ---------------------------------------------------------------------------
__global__ void __launch_bounds__(TPB, 4)
k_fused(const int*   __restrict__ dtok,
        const float* __restrict__ dp,
        const float* __restrict__ op,
        const float* __restrict__ unif,
        const float* __restrict__ su,
        float*       __restrict__ out)
{
    __shared__ float ssh[SEGC];

    int blk = blockIdx.x;
    int b = blk / NS, s = blk % NS;
    int t = threadIdx.x, lane = t & 31, wid = t >> 5;

    // ---- acceptance, computed redundantly per warp (L2-hot, no block sync) ----
    bool acc = false;
    if (lane < KK) {
        int tok  = dtok[b * KK + lane];
        float pd = dp[(b * KK + lane) * VV + tok];
        float po = op[(b * (KK + 1) + lane) * VV + tok];
        acc = unif[b * KK + lane] < fminf(1.0f, po / pd);
    }
    unsigned bits = __ballot_sync(FULL, acc) & ((1u << KK) - 1u);
    int na     = __ffs(~bits) - 1;          // 8 if all accepted
    int allacc = (na == KK);
    int r      = min(na, KK - 1);

    // ---- streaming loop: warp handles segments wid, wid+8, ... (< 100) ----
    int row = s * LCH;
    const float4* o4 = (const float4*)(op + (b * (KK + 1) + (allacc ? KK : r)) * VV + row);
    const float4* d4 = (const float4*)(dp + (b * KK + r) * VV + row);

#pragma unroll 4
    for (int jj = 0; jj < 13; ++jj) {
        int j = wid + jj * NW;
        if (j >= SEGC) break;               // uniform per warp
        float4 a = o4[j * 32 + lane];
        float p;
        if (allacc) {
            p = a.x + a.y + a.z + a.w;
        } else {
            float4 e = d4[j * 32 + lane];
            p = fmaxf(a.x - e.x, 0.f) + fmaxf(a.y - e.y, 0.f)
              + fmaxf(a.z - e.z, 0.f) + fmaxf(a.w - e.w, 0.f);
        }
#pragma unroll
        for (int o = 16; o > 0; o >>= 1)
            p += __shfl_down_sync(FULL, p, o);
        if (lane == 0) {
            ssh[j] = p;
            g_ssum[blk * SEGC + j] = p;
        }
    }

    // ---- token scaffolding (chunk s==0 writes all slots except na) ----
    if (s == 0) {
        if (t <= KK && t != na)
            out[b * (KK + 1) + t] = (t < na) ? (float)dtok[b * KK + t] : -1.0f;
        if (t == KK + 1)
            out[BB * (KK + 1) + b] = (float)na;
    }

    __syncthreads();                 // all g_ssum / ssh stores done
    if (wid != 0) return;            // only warp 0 continues (no more barriers)

    // ---- chunk sum in EXACT level-2 order: 4 group-scans with carry ----
    float run = 0.0f;
#pragma unroll
    for (int g = 0; g < 4; ++g) {
        int j = g * 32 + lane;
        float v = (j < SEGC) ? ssh[j] : 0.0f;
        float xx = v;
#pragma unroll
        for (int o = 1; o < 32; o <<= 1) {
            float y = __shfl_up_sync(FULL, xx, o);
            if (lane >= o) xx += y;
        }
        run += __shfl_sync(FULL, xx, 31);
    }
    if (lane == 0) g_chunksum[blk] = run;

    // ---- publish + elect last block of this batch (warp-local protocol) ----
    int last = 0;
    if (lane == 0) {
        __threadfence();             // make this block's sums device-visible
        int old = atomicAdd(&g_done[b], 1);
        last = (old == NS - 1);
        if (last) g_done[b] = 0;     // self-reset for graph replay
    }
    last = __shfl_sync(FULL, last, 0);
    if (!last) return;

    __threadfence();                 // acquire before cross-block reads
    cdf_search(b, na, allacc, r, dp, op, su, out, lane);
}

// ---------------------------------------------------------------------------
// Host launcher: classify inputs by element count (order-agnostic).
// ---------------------------------------------------------------------------
extern "C" void kernel_launch(void* const* d_in, const int* in_sizes, int n_in,
                              void* d_out, int out_size)
{
    const int*   dtok = nullptr;
    const float* dp   = nullptr;
    const float* op   = nullptr;
    const float* unif = nullptr;
    const float* su   = nullptr;

    int n512 = 0;
    for (int i = 0; i < n_in; ++i) {
        long sz = (long)in_sizes[i];
        if (sz == (long)BB * KK * VV)            dp = (const float*)d_in[i];
        else if (sz == (long)BB * (KK + 1) * VV) op = (const float*)d_in[i];
        else if (sz == BB)                       su = (const float*)d_in[i];
        else if (sz == BB * KK) {
            // relative order: draft_tokens, oracle_tokens, uniforms
            if      (n512 == 0) dtok = (const int*)d_in[i];
            else if (n512 == 2) unif = (const float*)d_in[i];
            ++n512;
        }
    }

    float* out = (float*)d_out;  // [tokens (B*(K+1)) | num_accepted (B)] as f32

    k_fused<<<BB * NS, TPB>>>(dtok, dp, op, unif, su, out);
}

// round 13
// speedup vs baseline: 1.2424x; 1.2424x over previous
#include <cuda_runtime.h>
#include <cstdint>

// Problem constants (shapes fixed by the dataset)
#define BB   64
#define KK   8
#define VV   128000
#define NS   25              // chunks per batch row
#define TPB  256
#define NW   (TPB / 32)      // 8 warps per block
#define LCH  (VV / NS)       // 5120 floats per chunk
#define SEG  128             // floats per segment (one warp-wide float4 iter)
#define SPW  5               // segments per warp (5*128 = 640 floats)
#define SEGS (NW * SPW)      // 40 segments per chunk
#define FULL 0xFFFFFFFFu

// Scratch (device globals). Kernel boundaries provide all synchronization:
// no atomics, fences or done-counters anywhere.
__device__ float g_ssum[BB * NS * SEGS];     // per-segment sums
__device__ float g_chunksum[BB * NS];
__device__ int   g_meta[BB];                 // na | allacc<<8 | r<<16

// ---------------------------------------------------------------------------
// Kernel 1: acceptance for all 64 batches in ONE block (512 threads).
// All 1024 scattered gathers are in flight simultaneously. Also writes the
// token scaffolding (every slot except position na) and num_accepted.
// ---------------------------------------------------------------------------
__global__ void __launch_bounds__(512)
k_accept(const int*   __restrict__ dtok,
         const float* __restrict__ dp,
         const float* __restrict__ op,
         const float* __restrict__ unif,
         float*       __restrict__ out)
{
    int t    = threadIdx.x;        // 0..511
    int b    = t >> 3;             // batch 0..63
    int k    = t & 7;              // draft position 0..7
    int lane = t & 31;

    int tok  = dtok[b * KK + k];
    float pd = dp[(b * KK + k) * VV + tok];
    float po = op[(b * (KK + 1) + k) * VV + tok];
    bool acc = unif[b * KK + k] < fminf(1.0f, po / pd);

    unsigned bal  = __ballot_sync(FULL, acc);
    unsigned bits = (bal >> (lane & 24)) & 0xFFu;   // this 8-lane group's bits
    int na = __ffs(~bits) - 1;                       // 8 if all accepted

    // scaffolding: thread k writes slot k; thread 0 also slot 8 (skip slot na)
    if (k != na)
        out[b * (KK + 1) + k] = (k < na) ? (float)tok : -1.0f;
    if (k == 0) {
        if (na != KK)
            out[b * (KK + 1) + KK] = -1.0f;          // slot 8 (na<8 case)
        out[BB * (KK + 1) + b] = (float)na;          // num_accepted block
        int allacc = (na == KK);
        int r      = min(na, KK - 1);
        g_meta[b]  = na | (allacc << 8) | (r << 16);
    }
}

// ---------------------------------------------------------------------------
// Kernel 2: pure streaming pass (R7 coalesced core). One chunk per block.
// Prologue = one L2-hot meta load. Epilogue = plain stores.
// ---------------------------------------------------------------------------
__global__ void __launch_bounds__(TPB, 4)
k_stream(const float* __restrict__ dp,
         const float* __restrict__ op)
{
    __shared__ float ssh[SEGS];

    int blk = blockIdx.x;
    int b = blk / NS, s = blk % NS;
    int t = threadIdx.x, lane = t & 31, wid = t >> 5;

    int meta   = g_meta[b];
    int allacc = (meta >> 8) & 1;
    int r      = meta >> 16;

    // ---- coalesced streaming: 5 oracle + 5 draft float4 loads up front ----
    int row  = s * LCH;
    int base = wid * (SPW * 32);
    const float4* o4 = (const float4*)(op + (b * (KK + 1) + (allacc ? KK : r)) * VV + row);
    const float4* d4 = (const float4*)(dp + (b * KK + r) * VV + row);

    float4 a0 = o4[base + 0 * 32 + lane];
    float4 a1 = o4[base + 1 * 32 + lane];
    float4 a2 = o4[base + 2 * 32 + lane];
    float4 a3 = o4[base + 3 * 32 + lane];
    float4 a4 = o4[base + 4 * 32 + lane];

    float p[SPW];
    if (allacc) {
        p[0] = a0.x + a0.y + a0.z + a0.w;
        p[1] = a1.x + a1.y + a1.z + a1.w;
        p[2] = a2.x + a2.y + a2.z + a2.w;
        p[3] = a3.x + a3.y + a3.z + a3.w;
        p[4] = a4.x + a4.y + a4.z + a4.w;
    } else {
        float4 e0 = d4[base + 0 * 32 + lane];
        float4 e1 = d4[base + 1 * 32 + lane];
        float4 e2 = d4[base + 2 * 32 + lane];
        float4 e3 = d4[base + 3 * 32 + lane];
        float4 e4 = d4[base + 4 * 32 + lane];
        p[0] = fmaxf(a0.x - e0.x, 0.f) + fmaxf(a0.y - e0.y, 0.f)
             + fmaxf(a0.z - e0.z, 0.f) + fmaxf(a0.w - e0.w, 0.f);
        p[1] = fmaxf(a1.x - e1.x, 0.f) + fmaxf(a1.y - e1.y, 0.f)
             + fmaxf(a1.z - e1.z, 0.f) + fmaxf(a1.w - e1.w, 0.f);
        p[2] = fmaxf(a2.x - e2.x, 0.f) + fmaxf(a2.y - e2.y, 0.f)
             + fmaxf(a2.z - e2.z, 0.f) + fmaxf(a2.w - e2.w, 0.f);
        p[3] = fmaxf(a3.x - e3.x, 0.f) + fmaxf(a3.y - e3.y, 0.f)
             + fmaxf(a3.z - e3.z, 0.f) + fmaxf(a3.w - e3.w, 0.f);
        p[4] = fmaxf(a4.x - e4.x, 0.f) + fmaxf(a4.y - e4.y, 0.f)
             + fmaxf(a4.z - e4.z, 0.f) + fmaxf(a4.w - e4.w, 0.f);
    }

    // ---- segment sums (5 independent warp tree-reduces) ----
#pragma unroll
    for (int i = 0; i < SPW; ++i) {
        float w = p[i];
#pragma unroll
        for (int o = 16; o > 0; o >>= 1)
            w += __shfl_down_sync(FULL, w, o);
        if (lane == 0) {
            ssh[wid * SPW + i] = w;
            g_ssum[blk * SEGS + wid * SPW + i] = w;
        }
    }

    __syncthreads();
    if (wid != 0) return;

    // chunk sum in EXACT level-2 search order: 2 group-scans with carry
    float run = 0.0f;
#pragma unroll
    for (int g = 0; g < 2; ++g) {
        int j = g * 32 + lane;
        float v = (j < SEGS) ? ssh[j] : 0.0f;
        float xx = v;
#pragma unroll
        for (int o = 1; o < 32; o <<= 1) {
            float y = __shfl_up_sync(FULL, xx, o);
            if (lane >= o) xx += y;
        }
        run += __shfl_sync(FULL, xx, 31);
    }
    if (lane == 0) g_chunksum[blk] = run;
}

// ---------------------------------------------------------------------------
// Kernel 3: hierarchical CDF search, one warp per batch (grid = 64).
// level 1: 25 chunk sums -> level 2: 40 segment sums -> level 3: 128 floats.
// ---------------------------------------------------------------------------
__global__ void __launch_bounds__(32)
k_search(const float* __restrict__ dp,
         const float* __restrict__ op,
         const float* __restrict__ su,
         float*       __restrict__ out)
{
    int b    = blockIdx.x;
    int lane = threadIdx.x;

    int meta   = g_meta[b];
    int na     = meta & 0xFF;
    int allacc = (meta >> 8) & 1;
    int r      = meta >> 16;

    float cs = (lane < NS) ? g_chunksum[b * NS + lane] : 0.0f;
    float x = cs;
#pragma unroll
    for (int o = 1; o < 32; o <<= 1) {
        float y = __shfl_up_sync(FULL, x, o);
        if (lane >= o) x += y;
    }
    float tot = __shfl_sync(FULL, x, NS - 1);
    float T = allacc ? su[b] : su[b] * tot;

    unsigned bal = __ballot_sync(FULL, (lane < NS) && (x >= T));
    int token;
    if (bal == 0) {
        token = VV - 1;
    } else {
        int sc = __ffs(bal) - 1;
        float base = __shfl_sync(FULL, x, sc) - __shfl_sync(FULL, cs, sc);

        // level 2: 40 segment sums, 2 group-scans with carry
        const float* ss = &g_ssum[(b * NS + sc) * SEGS];
        int   j_found = -1;
        float base_t  = 0.0f;
        float running = base;
#pragma unroll
        for (int g = 0; g < 2; ++g) {
            int j = g * 32 + lane;
            float v = (j < SEGS) ? ss[j] : 0.0f;
            float xx = v;
#pragma unroll
            for (int o = 1; o < 32; o <<= 1) {
                float y = __shfl_up_sync(FULL, xx, o);
                if (lane >= o) xx += y;
            }
            unsigned bb2 = __ballot_sync(FULL, (j < SEGS) && (running + xx >= T));
            if (bb2) {
                int l = __ffs(bb2) - 1;
                j_found = g * 32 + l;
                base_t  = running + __shfl_sync(FULL, xx, l)
                                  - __shfl_sync(FULL, v, l);
                break;
            }
            running += __shfl_sync(FULL, xx, 31);
        }

        if (j_found < 0) {
            token = min(sc * LCH + LCH, VV - 1);         // ulp-tie fallback
        } else {
            // level 3: one 128-float segment, coalesced re-read
            int off0 = sc * LCH + j_found * SEG;
            int ob2  = (b * (KK + 1) + (allacc ? KK : r)) * VV + off0;
            int db2  = (b * KK + r) * VV + off0;
            float4 ov = ((const float4*)(op + ob2))[lane];
            float v0, v1, v2, v3;
            if (allacc) {
                v0 = ov.x; v1 = ov.y; v2 = ov.z; v3 = ov.w;
            } else {
                float4 dv = ((const float4*)(dp + db2))[lane];
                v0 = fmaxf(ov.x - dv.x, 0.f); v1 = fmaxf(ov.y - dv.y, 0.f);
                v2 = fmaxf(ov.z - dv.z, 0.f); v3 = fmaxf(ov.w - dv.w, 0.f);
            }
            float local = v0 + v1 + v2 + v3;
            float xs = local;
#pragma unroll
            for (int o = 1; o < 32; o <<= 1) {
                float y = __shfl_up_sync(FULL, xs, o);
                if (lane >= o) xs += y;
            }
            unsigned bb3 = __ballot_sync(FULL, base_t + xs >= T);
            if (!bb3) {
                token = min(off0 + SEG, VV - 1);          // ulp-tie fallback
            } else {
                int l = __ffs(bb3) - 1;
                float excl = base_t + __shfl_sync(FULL, xs, l)
                                    - __shfl_sync(FULL, local, l);
                float a0 = __shfl_sync(FULL, v0, l);
                float a1 = __shfl_sync(FULL, v1, l);
                float a2 = __shfl_sync(FULL, v2, l);
                float run = excl;
                int idx = 3;
                run += a0;
                if (run >= T) idx = 0;
                else { run += a1;
                    if (run >= T) idx = 1;
                    else { run += a2; if (run >= T) idx = 2; }
                }
                token = min(off0 + l * 4 + idx, VV - 1);
            }
        }
    }

    if (lane == 0)
        out[b * (KK + 1) + na] = (float)token;
}

// ---------------------------------------------------------------------------
// Host launcher: classify inputs by element count (order-agnostic).
// ---------------------------------------------------------------------------
extern "C" void kernel_launch(void* const* d_in, const int* in_sizes, int n_in,
                              void* d_out, int out_size)
{
    const int*   dtok = nullptr;
    const float* dp   = nullptr;
    const float* op   = nullptr;
    const float* unif = nullptr;
    const float* su   = nullptr;

    int n512 = 0;
    for (int i = 0; i < n_in; ++i) {
        long sz = (long)in_sizes[i];
        if (sz == (long)BB * KK * VV)            dp = (const float*)d_in[i];
        else if (sz == (long)BB * (KK + 1) * VV) op = (const float*)d_in[i];
        else if (sz == BB)                       su = (const float*)d_in[i];
        else if (sz == BB * KK) {
            // relative order: draft_tokens, oracle_tokens, uniforms
            if      (n512 == 0) dtok = (const int*)d_in[i];
            else if (n512 == 2) unif = (const float*)d_in[i];
            ++n512;
        }
    }

    float* out = (float*)d_out;  // [tokens (B*(K+1)) | num_accepted (B)] as f32

    k_accept<<<1, 512>>>(dtok, dp, op, unif, out);
    k_stream<<<BB * NS, TPB>>>(dp, op);
    k_search<<<BB, 32>>>(dp, op, su, out);
}

// round 14
// speedup vs baseline: 1.2788x; 1.0292x over previous
#include <cuda_runtime.h>
#include <cstdint>

// Problem constants (shapes fixed by the dataset)
#define BB   64
#define KK   8
#define VV   128000
#define NS   50              // chunks per batch row
#define TPB  128
#define NW   (TPB / 32)      // 4 warps per block
#define LCH  (VV / NS)       // 2560 floats per chunk
#define SEG  128             // floats per segment (one warp-wide float4 iter)
#define SPW  5               // segments per warp (5*128 = 640 floats)
#define SEGS (NW * SPW)      // 20 segments per chunk
#define FULL 0xFFFFFFFFu

// Scratch (device globals — zero-initialized; g_done self-resets every call)
__device__ float g_ssum[BB * NS * SEGS];     // per-segment sums
__device__ float g_chunksum[BB * NS];
__device__ int   g_done[BB];

// ---------------------------------------------------------------------------
// Hierarchical CDF search for one batch (warp 0 of the last-done block).
// level 1: 50 chunk sums -> level 2: 20 segment sums -> level 3: 128 floats.
// All scan orders match exactly how the sums were constructed.
// ---------------------------------------------------------------------------
__device__ __forceinline__ void cdf_search(int b, int na, int allacc, int r,
                                           const float* __restrict__ dp,
                                           const float* __restrict__ op,
                                           const float* __restrict__ su,
                                           float* __restrict__ out, int lane)
{
    // ---- level 1: 50 chunk sums (two 32-wide groups, scanned with carry) ----
    float s0 = __ldcg(&g_chunksum[b * NS + lane]);                   // j = lane (<50)
    float s1 = (32 + lane < NS) ? __ldcg(&g_chunksum[b * NS + 32 + lane]) : 0.0f;
    float x0 = s0, x1 = s1;
#pragma unroll
    for (int o = 1; o < 32; o <<= 1) {
        float y0 = __shfl_up_sync(FULL, x0, o);
        float y1 = __shfl_up_sync(FULL, x1, o);
        if (lane >= o) { x0 += y0; x1 += y1; }
    }
    float x0t = __shfl_sync(FULL, x0, 31);
    float tot = x0t + __shfl_sync(FULL, x1, 31);
    float T = allacc ? su[b] : su[b] * tot;

    int sc = -1;
    float base = 0.0f;
    unsigned b0 = __ballot_sync(FULL, x0 >= T);
    if (b0) {
        int l = __ffs(b0) - 1;
        sc = l;
        base = __shfl_sync(FULL, x0, l) - __shfl_sync(FULL, s0, l);
    } else {
        unsigned b1 = __ballot_sync(FULL, (32 + lane < NS) && (x0t + x1 >= T));
        if (b1) {
            int l = __ffs(b1) - 1;
            sc = 32 + l;
            base = x0t + __shfl_sync(FULL, x1, l) - __shfl_sync(FULL, s1, l);
        }
    }

    int token;
    if (sc < 0) {
        token = VV - 1;                              // u beyond total mass
    } else {
        // ---- level 2: 20 segment sums of chunk sc (single group scan) ----
        float v = (lane < SEGS) ? __ldcg(&g_ssum[(b * NS + sc) * SEGS + lane]) : 0.0f;
        float xx = v;
#pragma unroll
        for (int o = 1; o < 32; o <<= 1) {
            float y = __shfl_up_sync(FULL, xx, o);
            if (lane >= o) xx += y;
        }
        unsigned b2 = __ballot_sync(FULL, (lane < SEGS) && (base + xx >= T));
        if (!b2) {
            token = min(sc * LCH + LCH, VV - 1);     // ulp-tie fallback
        } else {
            int j = __ffs(b2) - 1;
            float base_t = base + __shfl_sync(FULL, xx, j)
                                - __shfl_sync(FULL, v, j);

            // ---- level 3: one 128-float segment, coalesced re-read ----
            int off0 = sc * LCH + j * SEG;
            int ob2  = (b * (KK + 1) + (allacc ? KK : r)) * VV + off0;
            int db2  = (b * KK + r) * VV + off0;
            float4 ov = ((const float4*)(op + ob2))[lane];
            float v0, v1, v2, v3;
            if (allacc) {
                v0 = ov.x; v1 = ov.y; v2 = ov.z; v3 = ov.w;
            } else {
                float4 dv = ((const float4*)(dp + db2))[lane];
                v0 = fmaxf(ov.x - dv.x, 0.f); v1 = fmaxf(ov.y - dv.y, 0.f);
                v2 = fmaxf(ov.z - dv.z, 0.f); v3 = fmaxf(ov.w - dv.w, 0.f);
            }
            float local = v0 + v1 + v2 + v3;
            float xs = local;
#pragma unroll
            for (int o = 1; o < 32; o <<= 1) {
                float y = __shfl_up_sync(FULL, xs, o);
                if (lane >= o) xs += y;
            }
            unsigned b3 = __ballot_sync(FULL, base_t + xs >= T);
            if (!b3) {
                token = min(off0 + SEG, VV - 1);      // ulp-tie fallback
            } else {
                int l = __ffs(b3) - 1;
                float excl = base_t + __shfl_sync(FULL, xs, l)
                                    - __shfl_sync(FULL, local, l);
                float a0 = __shfl_sync(FULL, v0, l);
                float a1 = __shfl_sync(FULL, v1, l);
                float a2 = __shfl_sync(FULL, v2, l);
                float run = excl;
                int idx = 3;
                run += a0;
                if (run >= T) idx = 0;
                else { run += a1;
                    if (run >= T) idx = 1;
                    else { run += a2; if (run >= T) idx = 2; }
                }
                token = min(off0 + l * 4 + idx, VV - 1);
            }
        }
    }

    if (lane == 0)
        out[b * (KK + 1) + na] = (float)token;
}

// ---------------------------------------------------------------------------
// Fused kernel (R7 load core, 128-thread blocks): one 10.2KB-per-row chunk
// per block, grid = 3200. Per-warp acceptance overlaps other blocks' streams;
// single __syncthreads; warps 1-3 exit immediately after it.
// ---------------------------------------------------------------------------
__global__ void __launch_bounds__(TPB, 8)
k_fused(const int*   __restrict__ dtok,
        const float* __restrict__ dp,
        const float* __restrict__ op,
        const float* __restrict__ unif,
        const float* __restrict__ su,
        float*       __restrict__ out)
{
    __shared__ float ssh[SEGS];

    int blk = blockIdx.x;
    int b = blk / NS, s = blk % NS;
    int t = threadIdx.x, lane = t & 31, wid = t >> 5;

    // ---- acceptance, computed redundantly per warp (L2-hot) ----
    bool acc = false;
    if (lane < KK) {
        int tok  = dtok[b * KK + lane];
        float pd = dp[(b * KK + lane) * VV + tok];
        float po = op[(b * (KK + 1) + lane) * VV + tok];
        acc = unif[b * KK + lane] < fminf(1.0f, po / pd);
    }
    unsigned bits = __ballot_sync(FULL, acc) & ((1u << KK) - 1u);
    int na     = __ffs(~bits) - 1;          // 8 if all accepted
    int allacc = (na == KK);
    int r      = min(na, KK - 1);

    // ---- coalesced streaming: 5 oracle (+5 draft) float4 loads up front ----
    int row  = s * LCH;
    int base = wid * (SPW * 32);
    const float4* o4 = (const float4*)(op + (b * (KK + 1) + (allacc ? KK : r)) * VV + row);
    const float4* d4 = (const float4*)(dp + (b * KK + r) * VV + row);

    float4 a0 = o4[base + 0 * 32 + lane];
    float4 a1 = o4[base + 1 * 32 + lane];
    float4 a2 = o4[base + 2 * 32 + lane];
    float4 a3 = o4[base + 3 * 32 + lane];
    float4 a4 = o4[base + 4 * 32 + lane];

    float p[SPW];
    if (allacc) {
        p[0] = a0.x + a0.y + a0.z + a0.w;
        p[1] = a1.x + a1.y + a1.z + a1.w;
        p[2] = a2.x + a2.y + a2.z + a2.w;
        p[3] = a3.x + a3.y + a3.z + a3.w;
        p[4] = a4.x + a4.y + a4.z + a4.w;
    } else {
        float4 e0 = d4[base + 0 * 32 + lane];
        float4 e1 = d4[base + 1 * 32 + lane];
        float4 e2 = d4[base + 2 * 32 + lane];
        float4 e3 = d4[base + 3 * 32 + lane];
        float4 e4 = d4[base + 4 * 32 + lane];
        p[0] = fmaxf(a0.x - e0.x, 0.f) + fmaxf(a0.y - e0.y, 0.f)
             + fmaxf(a0.z - e0.z, 0.f) + fmaxf(a0.w - e0.w, 0.f);
        p[1] = fmaxf(a1.x - e1.x, 0.f) + fmaxf(a1.y - e1.y, 0.f)
             + fmaxf(a1.z - e1.z, 0.f) + fmaxf(a1.w - e1.w, 0.f);
        p[2] = fmaxf(a2.x - e2.x, 0.f) + fmaxf(a2.y - e2.y, 0.f)
             + fmaxf(a2.z - e2.z, 0.f) + fmaxf(a2.w - e2.w, 0.f);
        p[3] = fmaxf(a3.x - e3.x, 0.f) + fmaxf(a3.y - e3.y, 0.f)
             + fmaxf(a3.z - e3.z, 0.f) + fmaxf(a3.w - e3.w, 0.f);
        p[4] = fmaxf(a4.x - e4.x, 0.f) + fmaxf(a4.y - e4.y, 0.f)
             + fmaxf(a4.z - e4.z, 0.f) + fmaxf(a4.w - e4.w, 0.f);
    }

    // ---- segment sums (5 independent warp tree-reduces) ----
#pragma unroll
    for (int i = 0; i < SPW; ++i) {
        float w = p[i];
#pragma unroll
        for (int o = 16; o > 0; o >>= 1)
            w += __shfl_down_sync(FULL, w, o);
        if (lane == 0) {
            ssh[wid * SPW + i] = w;
            g_ssum[blk * SEGS + wid * SPW + i] = w;
        }
    }

    // ---- token scaffolding (chunk s==0 writes all slots except na) ----
    if (s == 0) {
        if (t <= KK && t != na)
            out[b * (KK + 1) + t] = (t < na) ? (float)dtok[b * KK + t] : -1.0f;
        if (t == KK + 1)
            out[BB * (KK + 1) + b] = (float)na;
    }

    __syncthreads();                 // ssh / g_ssum stores done
    if (wid != 0) return;            // warps 1-3 retire immediately

    // ---- chunk sum: single group-scan (same order as level-2 search) ----
    float v = (lane < SEGS) ? ssh[lane] : 0.0f;
    float xx = v;
#pragma unroll
    for (int o = 1; o < 32; o <<= 1) {
        float y = __shfl_up_sync(FULL, xx, o);
        if (lane >= o) xx += y;
    }
    float csum = __shfl_sync(FULL, xx, 31);

    // ---- publish + elect last block of this batch (warp-local protocol) ----
    int last = 0;
    if (lane == 0) {
        g_chunksum[blk] = csum;
        __threadfence();             // make this block's sums device-visible
        int old = atomicAdd(&g_done[b], 1);
        last = (old == NS - 1);
        if (last) g_done[b] = 0;     // self-reset for graph replay
    }
    last = __shfl_sync(FULL, last, 0);
    if (!last) return;

    __threadfence();                 // acquire before cross-block reads
    cdf_search(b, na, allacc, r, dp, op, su, out, lane);
}

// ---------------------------------------------------------------------------
// Host launcher: classify inputs by element count (order-agnostic).
// ---------------------------------------------------------------------------
extern "C" void kernel_launch(void* const* d_in, const int* in_sizes, int n_in,
                              void* d_out, int out_size)
{
    const int*   dtok = nullptr;
    const float* dp   = nullptr;
    const float* op   = nullptr;
    const float* unif = nullptr;
    const float* su   = nullptr;

    int n512 = 0;
    for (int i = 0; i < n_in; ++i) {
        long sz = (long)in_sizes[i];
        if (sz == (long)BB * KK * VV)            dp = (const float*)d_in[i];
        else if (sz == (long)BB * (KK + 1) * VV) op = (const float*)d_in[i];
        else if (sz == BB)                       su = (const float*)d_in[i];
        else if (sz == BB * KK) {
            // relative order: draft_tokens, oracle_tokens, uniforms
            if      (n512 == 0) dtok = (const int*)d_in[i];
            else if (n512 == 2) unif = (const float*)d_in[i];
            ++n512;
        }
    }

    float* out = (float*)d_out;  // [tokens (B*(K+1)) | num_accepted (B)] as f32

    k_fused<<<BB * NS, TPB>>>(dtok, dp, op, unif, su, out);
}